// round 17
// baseline (speedup 1.0000x reference)
#include <cuda_runtime.h>
#include <cuda_bf16.h>
#include <cstdint>

// Problem constants
#define BATCH   2
#define SEQ     2048
#define DMODEL  1024
#define NHEADS  16
#define HDIM    64
#define MTOT    (BATCH * SEQ)          // 4096

// Scratch (device globals; no allocations allowed)
// Q/K hold tf32-rounded bits in [b,h,s,d]; V holds tf32-rounded bits
// TRANSPOSED per head: [b,h,d,s] (written by projection epilogue mode 2).
__device__ float g_Q[BATCH * NHEADS * SEQ * HDIM];
__device__ float g_K[BATCH * NHEADS * SEQ * HDIM];
__device__ float g_V[BATCH * NHEADS * SEQ * HDIM];
__device__ float g_attn[MTOT * DMODEL];                // [b*s, h*d]

__device__ __forceinline__ uint32_t f2tf32(float f) {
    uint32_t r;
    asm("cvt.rna.tf32.f32 %0, %1;" : "=r"(r) : "f"(f));
    return r;
}

#define MMA_TF32(C, A, B0, B1)                                              \
    asm volatile(                                                           \
        "mma.sync.aligned.m16n8k8.row.col.f32.tf32.tf32.f32 "               \
        "{%0,%1,%2,%3}, {%4,%5,%6,%7}, {%8,%9}, {%0,%1,%2,%3};"             \
        : "+f"((C)[0]), "+f"((C)[1]), "+f"((C)[2]), "+f"((C)[3])            \
        : "r"((A)[0]), "r"((A)[1]), "r"((A)[2]), "r"((A)[3]),               \
          "r"(B0), "r"(B1))

#define CP_ASYNC16(dst, src)                                                \
    asm volatile("cp.async.ca.shared.global [%0], [%1], 16;"                \
                 :: "r"(dst), "l"(src))
#define CP_COMMIT()  asm volatile("cp.async.commit_group;" ::: "memory")
#define CP_WAIT(n)   asm volatile("cp.async.wait_group %0;" :: "n"(n) : "memory")

#define LDSM4(R, addr)                                                      \
    asm volatile("ldmatrix.sync.aligned.m8n8.x4.shared.b16 "                \
                 "{%0,%1,%2,%3}, [%4];"                                     \
                 : "=r"((R)[0]), "=r"((R)[1]), "=r"((R)[2]), "=r"((R)[3])   \
                 : "r"(addr))

// ---------------------------------------------------------------------------
// tf32 tensor-core GEMM body: out[m][n] = X[m][:] @ W[:][n] + bias[n]
// 128x128x16 tile, 8 warps (4x2), warp 32x64 via m16n8k8, double-buffered.
// A-fragments via ldmatrix.x4 (stride-20 conflict-free); B scalar.
// mode 0: tf32-rounded scatter to [b,h,s,d]
// mode 2: tf32-rounded scatter to [b,h,d,s]  (transposed; for V)
// mode 1: plain fp32 [m][n]
// ---------------------------------------------------------------------------
#define SA 20
#define SB 136

__device__ __forceinline__ void gemm_body(
    const float* __restrict__ X, const float* __restrict__ W,
    const float* __restrict__ bias, float* __restrict__ out, int mode) {
    __shared__ uint32_t As[2][128][SA];   // [m][k]
    __shared__ uint32_t Bs[2][16][SB];    // [k][n]

    const int tid  = threadIdx.x;
    const int lane = tid & 31;
    const int warp = tid >> 5;
    const int g = lane >> 2;
    const int t = lane & 3;
    const int wm = (warp >> 1) * 32;
    const int wn = (warp & 1) * 64;
    const int m0 = blockIdx.y * 128;
    const int n0 = blockIdx.x * 128;

    const int am[2]  = { tid >> 2, (tid + 256) >> 2 };
    const int ak[2]  = { (tid & 3) * 4, (tid & 3) * 4 };
    const int bk[2]  = { tid >> 5, (tid + 256) >> 5 };
    const int bn[2]  = { (tid & 31) * 4, (tid & 31) * 4 };

    const int arow  = (lane & 7) + ((lane >> 3) & 1) * 8;
    const int acol4 = (lane >> 4) * 4;
    const uint32_t As_u = (uint32_t)__cvta_generic_to_shared(&As[0][0][0]);

    const float* Xp = X + (size_t)m0 * DMODEL;
    const float* Wp = W + n0;

    float c[2][8][4];
#pragma unroll
    for (int mt = 0; mt < 2; mt++)
#pragma unroll
        for (int ni = 0; ni < 8; ni++)
#pragma unroll
            for (int r = 0; r < 4; r++) c[mt][ni][r] = 0.f;

    float4 ra[2], rb[2];

#pragma unroll
    for (int i = 0; i < 2; i++) {
        ra[i] = *(const float4*)(Xp + (size_t)am[i] * DMODEL + ak[i]);
        rb[i] = *(const float4*)(Wp + (size_t)bk[i] * DMODEL + bn[i]);
    }
#pragma unroll
    for (int i = 0; i < 2; i++) {
        uint32_t* ap = &As[0][am[i]][ak[i]];
        ap[0] = f2tf32(ra[i].x); ap[1] = f2tf32(ra[i].y);
        ap[2] = f2tf32(ra[i].z); ap[3] = f2tf32(ra[i].w);
        uint32_t* bp = &Bs[0][bk[i]][bn[i]];
        bp[0] = f2tf32(rb[i].x); bp[1] = f2tf32(rb[i].y);
        bp[2] = f2tf32(rb[i].z); bp[3] = f2tf32(rb[i].w);
    }
    __syncthreads();

    int buf = 0;
    const int NITER = DMODEL / 16;   // 64
    for (int it = 0; it < NITER; it++) {
        const int k_next = (it + 1) * 16;
        if (it + 1 < NITER) {
#pragma unroll
            for (int i = 0; i < 2; i++) {
                ra[i] = *(const float4*)(Xp + (size_t)am[i] * DMODEL + k_next + ak[i]);
                rb[i] = *(const float4*)(Wp + (size_t)(k_next + bk[i]) * DMODEL + bn[i]);
            }
        }

#pragma unroll
        for (int ks = 0; ks < 2; ks++) {
            const int kk = ks * 8;
            uint32_t a[2][4];
#pragma unroll
            for (int mt = 0; mt < 2; mt++) {
                const uint32_t addr = As_u +
                    (uint32_t)(((buf * 128 + wm + mt * 16 + arow) * SA + kk + acol4) * 4);
                LDSM4(a[mt], addr);
            }
#pragma unroll
            for (int ni = 0; ni < 8; ni++) {
                const uint32_t b0 = Bs[buf][kk + t    ][wn + ni * 8 + g];
                const uint32_t b1 = Bs[buf][kk + t + 4][wn + ni * 8 + g];
#pragma unroll
                for (int mt = 0; mt < 2; mt++) {
                    MMA_TF32(c[mt][ni], a[mt], b0, b1);
                }
            }
        }

        if (it + 1 < NITER) {
            const int nb = buf ^ 1;
#pragma unroll
            for (int i = 0; i < 2; i++) {
                uint32_t* ap = &As[nb][am[i]][ak[i]];
                ap[0] = f2tf32(ra[i].x); ap[1] = f2tf32(ra[i].y);
                ap[2] = f2tf32(ra[i].z); ap[3] = f2tf32(ra[i].w);
                uint32_t* bp = &Bs[nb][bk[i]][bn[i]];
                bp[0] = f2tf32(rb[i].x); bp[1] = f2tf32(rb[i].y);
                bp[2] = f2tf32(rb[i].z); bp[3] = f2tf32(rb[i].w);
            }
            __syncthreads();
            buf = nb;
        }
    }

#pragma unroll
    for (int ni = 0; ni < 8; ni++) {
        const int col = n0 + wn + ni * 8 + 2 * t;
        const float2 bb = *(const float2*)(bias + col);
#pragma unroll
        for (int mt = 0; mt < 2; mt++) {
            const int row0 = m0 + wm + mt * 16 + g;
#pragma unroll
            for (int half = 0; half < 2; half++) {
                const int m = row0 + half * 8;
                float2 r;
                r.x = c[mt][ni][half * 2 + 0] + bb.x;
                r.y = c[mt][ni][half * 2 + 1] + bb.y;
                if (mode == 0) {
                    r.x = __uint_as_float(f2tf32(r.x));
                    r.y = __uint_as_float(f2tf32(r.y));
                    const int b = m >> 11, s = m & 2047;
                    const int h = col >> 6, d = col & 63;
                    *(float2*)(out + (((size_t)b * NHEADS + h) * SEQ + s) * HDIM + d) = r;
                } else if (mode == 2) {
                    r.x = __uint_as_float(f2tf32(r.x));
                    r.y = __uint_as_float(f2tf32(r.y));
                    const int b = m >> 11, s = m & 2047;
                    const int h = col >> 6, d = col & 63;
                    float* base = out + (((size_t)b * NHEADS + h) * HDIM + d) * SEQ + s;
                    base[0]   = r.x;   // d
                    base[SEQ] = r.y;   // d+1
                } else {
                    *(float2*)(out + (size_t)m * DMODEL + col) = r;
                }
            }
        }
    }
}

__global__ __launch_bounds__(256, 2) void gemm_tf32_kernel(
    const float* __restrict__ X, const float* __restrict__ W,
    const float* __restrict__ bias, float* __restrict__ out, int mode) {
    gemm_body(X, W, bias, out, mode);
}

// Fused Q/K/V projections; V written transposed (mode 2)
__global__ __launch_bounds__(256, 2) void gemm_qkv_kernel(
    const float* __restrict__ xq, const float* __restrict__ xk, const float* __restrict__ xv,
    const float* __restrict__ Wq, const float* __restrict__ Wk, const float* __restrict__ Wv,
    const float* __restrict__ bq, const float* __restrict__ bk, const float* __restrict__ bv,
    float* __restrict__ oq, float* __restrict__ ok, float* __restrict__ ov) {
    const int z = blockIdx.z;
    const float* X = (z == 0) ? xq : (z == 1) ? xk : xv;
    const float* W = (z == 0) ? Wq : (z == 1) ? Wk : Wv;
    const float* B = (z == 0) ? bq : (z == 1) ? bk : bv;
    float*       O = (z == 0) ? oq : (z == 1) ? ok : ov;
    gemm_body(X, W, B, O, (z == 2) ? 2 : 0);
}

// ---------------------------------------------------------------------------
// tf32 tensor-core flash attention, cp.async double-buffered K/V^T pipeline.
// Block = 64 q-rows x (head, batch); 128 threads, 3 CTAs/SM.
// S-phase K fragments AND PV-phase V fragments via ldmatrix.x4 (V arrives
// transposed [d][key] from the projection, so its smem tile is d-major with
// the same conflict-free stride-68 layout as K).
// ---------------------------------------------------------------------------
#define BQ 64
#define BK 64
#define SKK 68
#define SVT 68
#define KW   (BK * SKK)          // 4352 words
#define VW   (HDIM * SVT)        // 4352 words
#define STAGEW (KW + VW)         // 8704 words
#define ATTN_SMEM_BYTES (2 * STAGEW * 4)   // 69632

extern __shared__ uint32_t dsm[];

__global__ __launch_bounds__(128, 3) void attn_tf32_kernel(
    const float* __restrict__ Q, const float* __restrict__ K,
    const float* __restrict__ V, float* __restrict__ Out) {
    const int tid  = threadIdx.x;
    const int lane = tid & 31;
    const int warp = tid >> 5;
    const int g = lane >> 2;
    const int t = lane & 3;
    const int q0 = blockIdx.x * BQ;
    const int h  = blockIdx.y;
    const int b  = blockIdx.z;
    const size_t bh = (size_t)b * NHEADS + h;
    const float* Qb = Q + bh * SEQ * HDIM;
    const float* Kb = K + bh * SEQ * HDIM;
    const float* Vb = V + bh * SEQ * HDIM;   // transposed block: [d][s]

    const uint32_t dsm_u = (uint32_t)__cvta_generic_to_shared(dsm);

    // Q fragments: gmem holds tf32 bits; x0.125 is exact -> use bits directly.
    uint32_t qa[8][4];
    {
        const float* Qw = Qb + (size_t)(q0 + warp * 16) * HDIM;
#pragma unroll
        for (int ks = 0; ks < 8; ks++) {
            qa[ks][0] = __float_as_uint(0.125f * Qw[g       * HDIM + 8 * ks + t]);
            qa[ks][1] = __float_as_uint(0.125f * Qw[(g + 8) * HDIM + 8 * ks + t]);
            qa[ks][2] = __float_as_uint(0.125f * Qw[g       * HDIM + 8 * ks + t + 4]);
            qa[ks][3] = __float_as_uint(0.125f * Qw[(g + 8) * HDIM + 8 * ks + t + 4]);
        }
    }

    float o[8][4];
#pragma unroll
    for (int ni = 0; ni < 8; ni++)
#pragma unroll
        for (int rq = 0; rq < 4; rq++) o[ni][rq] = 0.f;
    float m0 = -1e30f, m1 = -1e30f, l0 = 0.f, l1 = 0.f;

    const int qb = lane & ~3;
    const int s0 = qb + (t >> 1);
    const int s1 = s0 + 2;

    // ldmatrix thread->address pieces (shared by K and V^T tiles)
    const int krow  = lane & 7;
    const int kcol4 = (lane >> 3) * 4;

    // Staging: K tile 64 keys x 64 d; V^T tile 64 d x 64 keys. Both 1024
    // 16B-chunks; thread handles 8 of each.
    auto stage_tile = [&](int stage, int kt) {
        uint32_t* sK  = dsm + stage * STAGEW;
        uint32_t* sVT = sK + KW;
        const float* Kg = Kb + (size_t)kt * HDIM;
        const float* Vg = Vb + kt;                 // row d: Vb + d*SEQ + kt
#pragma unroll
        for (int i = 0; i < 8; i++) {
            const int idx = tid + i * 128;
            const int rr = idx >> 4;               // K: key row / V^T: d row
            const int c4 = (idx & 15) * 4;         // K: d words / V^T: key words
            unsigned dk = (unsigned)__cvta_generic_to_shared(&sK[rr * SKK + c4]);
            CP_ASYNC16(dk, Kg + (size_t)rr * HDIM + c4);
            unsigned dv = (unsigned)__cvta_generic_to_shared(&sVT[rr * SVT + c4]);
            CP_ASYNC16(dv, Vg + (size_t)rr * SEQ + c4);
        }
    };

    stage_tile(0, 0);
    CP_COMMIT();

    int buf = 0;
    for (int kt = 0; kt < SEQ; kt += BK) {
        if (kt + BK < SEQ) {
            stage_tile(buf ^ 1, kt + BK);
            CP_COMMIT();
            CP_WAIT(1);
        } else {
            CP_WAIT(0);
        }
        __syncthreads();

        const uint32_t sKu  = dsm_u + (uint32_t)(buf * STAGEW * 4);
        const uint32_t sVTu = sKu + (uint32_t)(KW * 4);

        // S = (Q/8) @ K^T : K fragments via ldmatrix.x4
        float c[8][4];
#pragma unroll
        for (int ni = 0; ni < 8; ni++) {
            c[ni][0] = c[ni][1] = c[ni][2] = c[ni][3] = 0.f;
            const uint32_t rowbase = sKu +
                (uint32_t)(((ni * 8 + krow) * SKK + kcol4) * 4);
#pragma unroll
            for (int p = 0; p < 4; p++) {
                uint32_t bf[4];
                LDSM4(bf, rowbase + p * 64);
                MMA_TF32(c[ni], qa[2 * p    ], bf[0], bf[1]);
                MMA_TF32(c[ni], qa[2 * p + 1], bf[2], bf[3]);
            }
        }

        // Online softmax
        float pm0 = c[0][0], pm1 = c[0][2];
#pragma unroll
        for (int ni = 0; ni < 8; ni++) {
            pm0 = fmaxf(pm0, fmaxf(c[ni][0], c[ni][1]));
            pm1 = fmaxf(pm1, fmaxf(c[ni][2], c[ni][3]));
        }
        pm0 = fmaxf(pm0, __shfl_xor_sync(0xffffffffu, pm0, 1));
        pm0 = fmaxf(pm0, __shfl_xor_sync(0xffffffffu, pm0, 2));
        pm1 = fmaxf(pm1, __shfl_xor_sync(0xffffffffu, pm1, 1));
        pm1 = fmaxf(pm1, __shfl_xor_sync(0xffffffffu, pm1, 2));

        const float mn0 = fmaxf(m0, pm0);
        const float mn1 = fmaxf(m1, pm1);
        float rs0 = 0.f, rs1 = 0.f;
#pragma unroll
        for (int ni = 0; ni < 8; ni++) {
            c[ni][0] = __expf(c[ni][0] - mn0);
            c[ni][1] = __expf(c[ni][1] - mn0);
            c[ni][2] = __expf(c[ni][2] - mn1);
            c[ni][3] = __expf(c[ni][3] - mn1);
            rs0 += c[ni][0] + c[ni][1];
            rs1 += c[ni][2] + c[ni][3];
        }
        rs0 += __shfl_xor_sync(0xffffffffu, rs0, 1);
        rs0 += __shfl_xor_sync(0xffffffffu, rs0, 2);
        rs1 += __shfl_xor_sync(0xffffffffu, rs1, 1);
        rs1 += __shfl_xor_sync(0xffffffffu, rs1, 2);

        const float alpha0 = __expf(m0 - mn0);
        const float alpha1 = __expf(m1 - mn1);
        l0 = l0 * alpha0 + rs0;  m0 = mn0;
        l1 = l1 * alpha1 + rs1;  m1 = mn1;
#pragma unroll
        for (int ni = 0; ni < 8; ni++) {
            o[ni][0] *= alpha0; o[ni][1] *= alpha0;
            o[ni][2] *= alpha1; o[ni][3] *= alpha1;
        }

        // Relayout P: C-fragment (cols 2t,2t+1) -> A-fragment (cols t, t+4)
        uint32_t pa[8][4];
#pragma unroll
        for (int jj = 0; jj < 8; jj++) {
            const float v00 = __shfl_sync(0xffffffffu, c[jj][0], s0);
            const float v01 = __shfl_sync(0xffffffffu, c[jj][1], s0);
            const float v02 = __shfl_sync(0xffffffffu, c[jj][0], s1);
            const float v03 = __shfl_sync(0xffffffffu, c[jj][1], s1);
            const float v10 = __shfl_sync(0xffffffffu, c[jj][2], s0);
            const float v11 = __shfl_sync(0xffffffffu, c[jj][3], s0);
            const float v12 = __shfl_sync(0xffffffffu, c[jj][2], s1);
            const float v13 = __shfl_sync(0xffffffffu, c[jj][3], s1);
            pa[jj][0] = f2tf32((t & 1) ? v01 : v00);
            pa[jj][1] = f2tf32((t & 1) ? v11 : v10);
            pa[jj][2] = f2tf32((t & 1) ? v03 : v02);
            pa[jj][3] = f2tf32((t & 1) ? v13 : v12);
        }

        // O += P @ V : V fragments via ldmatrix.x4 on the transposed tile.
        // Tile p covers keys [16p,16p+16): bf[0],bf[1] -> jj=2p; bf[2],bf[3]
        // -> jj=2p+1. Accumulation order per o[ni] is jj=0..7, unchanged.
#pragma unroll
        for (int p = 0; p < 4; p++) {
#pragma unroll
            for (int ni = 0; ni < 8; ni++) {
                const uint32_t rowbase = sVTu +
                    (uint32_t)(((ni * 8 + krow) * SVT + kcol4) * 4);
                uint32_t bf[4];
                LDSM4(bf, rowbase + p * 64);
                MMA_TF32(o[ni], pa[2 * p    ], bf[0], bf[1]);
                MMA_TF32(o[ni], pa[2 * p + 1], bf[2], bf[3]);
            }
        }

        __syncthreads();
        buf ^= 1;
    }

    const float inv0 = 1.0f / l0;
    const float inv1 = 1.0f / l1;
    const int r0 = q0 + warp * 16 + g;
    const int r1 = r0 + 8;
#pragma unroll
    for (int ni = 0; ni < 8; ni++) {
        const int col = h * HDIM + ni * 8 + 2 * t;
        float2 w0 = make_float2(o[ni][0] * inv0, o[ni][1] * inv0);
        float2 w1 = make_float2(o[ni][2] * inv1, o[ni][3] * inv1);
        *(float2*)(Out + ((size_t)b * SEQ + r0) * DMODEL + col) = w0;
        *(float2*)(Out + ((size_t)b * SEQ + r1) * DMODEL + col) = w1;
    }
}

// ---------------------------------------------------------------------------
extern "C" void kernel_launch(void* const* d_in, const int* in_sizes, int n_in,
                              void* d_out, int out_size) {
    const float* q  = (const float*)d_in[0];
    const float* k  = (const float*)d_in[1];
    const float* v  = (const float*)d_in[2];
    const float* Wq = (const float*)d_in[3];
    const float* bq = (const float*)d_in[4];
    const float* Wk = (const float*)d_in[5];
    const float* bk = (const float*)d_in[6];
    const float* Wv = (const float*)d_in[7];
    const float* bv = (const float*)d_in[8];
    const float* Wo = (const float*)d_in[9];
    const float* bo = (const float*)d_in[10];
    float* out = (float*)d_out;

    float *gq, *gk, *gv, *ga;
    cudaGetSymbolAddress((void**)&gq, g_Q);
    cudaGetSymbolAddress((void**)&gk, g_K);
    cudaGetSymbolAddress((void**)&gv, g_V);
    cudaGetSymbolAddress((void**)&ga, g_attn);

    static bool attr_done = false;
    if (!attr_done) {
        cudaFuncSetAttribute(attn_tf32_kernel,
                             cudaFuncAttributeMaxDynamicSharedMemorySize,
                             ATTN_SMEM_BYTES);
        attr_done = true;
    }

    // Fused Q/K/V projections: one launch, grid (8, 32, 3); V transposed
    dim3 qkv_grid(DMODEL / 128, MTOT / 128, 3);
    gemm_qkv_kernel<<<qkv_grid, dim3(256)>>>(q, k, v, Wq, Wk, Wv, bq, bk, bv, gq, gk, gv);

    dim3 attn_grid(SEQ / BQ, NHEADS, BATCH);    // (32, 16, 2) = 1024 CTAs
    attn_tf32_kernel<<<attn_grid, dim3(128), ATTN_SMEM_BYTES>>>(gq, gk, gv, ga);

    dim3 gemm_grid(DMODEL / 128, MTOT / 128);   // (8, 32)
    gemm_tf32_kernel<<<gemm_grid, dim3(256)>>>(ga, Wo, bo, out, 1);
}